// round 16
// baseline (speedup 1.0000x reference)
#include <cuda_runtime.h>
#include <cuda_fp16.h>
#include <math.h>
#include <stdint.h>

// Problem constants
#define B_ 64
#define S_ 100
#define D_ 1024
#define H_ 16
#define F_ 4096
#define DEPTH_ 64
#define BS_ (B_ * S_)          // 6400
#define N_QKV 3072
#define EPS_ 1e-6f

// ---------------------------------------------------------------------------
// Scratch (device globals; no allocations allowed)
// ---------------------------------------------------------------------------
__device__ float g_pe[S_ * D_];
__device__ float g_x[BS_ * D_];          // fp32 residual
__device__ __half g_xh[BS_ * D_];        // fp16 GEMM A operand
__device__ __half g_WqkvTh[N_QKV * D_];  // [N,K] fp16
__device__ float g_bqkv[N_QKV];
__device__ __half g_WoTh[D_ * D_];       // [N,K] fp16
__device__ __half g_W1Th[F_ * D_];       // [N,K] fp16
__device__ __half g_W2Th[D_ * F_];       // [N,K] fp16
__device__ __half g_QKVh[BS_ * N_QKV];   // fp16 QKV
__device__ __half g_ctxh[BS_ * D_];      // fp16 attention output
__device__ float g_t1[2 * BS_ * D_];     // split-K fp32 partials / pre-LN buffer
__device__ float g_x1[BS_ * D_];         // fp32 residual
__device__ __half g_x1h[BS_ * D_];       // fp16 twin
__device__ __half g_ffhh[BS_ * F_];      // fp16 relu output

__device__ __forceinline__ void mma_f16(float* d, const uint32_t* a, const uint32_t* b) {
    asm volatile(
        "mma.sync.aligned.m16n8k16.row.col.f32.f16.f16.f32 "
        "{%0,%1,%2,%3}, {%4,%5,%6,%7}, {%8,%9}, {%0,%1,%2,%3};\n"
        : "+f"(d[0]), "+f"(d[1]), "+f"(d[2]), "+f"(d[3])
        : "r"(a[0]), "r"(a[1]), "r"(a[2]), "r"(a[3]), "r"(b[0]), "r"(b[1]));
}

// ---------------------------------------------------------------------------
// Positional encoding (fp32). log2(10000) = 13.287712379549449.
// ---------------------------------------------------------------------------
__global__ void pe_kernel(float* __restrict__ pe) {
    int idx = blockIdx.x * blockDim.x + threadIdx.x;
    if (idx >= S_ * D_) return;
    int s = idx / D_;
    int d = idx % D_;
    int k2 = d & ~1;
    float div = exp2f((float)k2 * (13.2877123795494f / (float)D_));
    float arg = (float)s / div;
    pe[idx] = (d & 1) ? cosf(arg) : sinf(arg);
}

// ---------------------------------------------------------------------------
// Embedding gather + positional add; fp32 x, fp16 xh. Also concats QKV bias.
// ---------------------------------------------------------------------------
__global__ void embed_kernel(const int* __restrict__ tokens,
                             const float* __restrict__ emb,
                             const float* __restrict__ pe,
                             float* __restrict__ x, __half* __restrict__ xh,
                             const float* __restrict__ bq, const float* __restrict__ bk,
                             const float* __restrict__ bv, float* __restrict__ bqkv) {
    int idx = blockIdx.x * blockDim.x + threadIdx.x;
    if (idx < N_QKV) {
        int which = idx / D_;
        int n = idx % D_;
        const float* bb = (which == 0) ? bq : ((which == 1) ? bk : bv);
        bqkv[idx] = bb[n];
    }
    if (idx >= BS_ * D_ / 4) return;
    int row = idx / (D_ / 4);
    int c4 = idx % (D_ / 4);
    int tok = tokens[row];
    float4 e = ((const float4*)(emb + (size_t)tok * D_))[c4];
    float4 p = ((const float4*)(pe + (size_t)(row % S_) * D_))[c4];
    float4 o;
    o.x = e.x + p.x; o.y = e.y + p.y; o.z = e.z + p.z; o.w = e.w + p.w;
    ((float4*)x)[idx] = o;
    ((__half2*)xh)[idx * 2 + 0] = __floats2half2_rn(o.x, o.y);
    ((__half2*)xh)[idx * 2 + 1] = __floats2half2_rn(o.z, o.w);
}

// ---------------------------------------------------------------------------
// QKV weight transpose: W{q,k,v}[H,D,64] -> WqkvTh[3072, 1024] fp16 ([N,K])
// ---------------------------------------------------------------------------
__global__ void qkvT_kernel(const float* __restrict__ Wq, const float* __restrict__ Wk,
                            const float* __restrict__ Wv, __half* __restrict__ Wt) {
    __shared__ float t[32][33];
    int z = blockIdx.z;
    int which = z / H_, h = z % H_;
    const float* W = (which == 0) ? Wq : ((which == 1) ? Wk : Wv);
    const float* src = W + (size_t)h * D_ * DEPTH_;
    int e0 = blockIdx.x * 32, d0 = blockIdx.y * 32;
    int tx = threadIdx.x, ty = threadIdx.y;
    for (int i = ty; i < 32; i += 8)
        t[i][tx] = src[(size_t)(d0 + i) * DEPTH_ + e0 + tx];
    __syncthreads();
    __half* dst = Wt + ((size_t)which * D_ + h * DEPTH_) * D_;
    for (int i = ty; i < 32; i += 8)
        dst[(size_t)(e0 + i) * D_ + d0 + tx] = __float2half_rn(t[tx][i]);
}

// ---------------------------------------------------------------------------
// Merged transpose of Wo, W1, W2 -> fp16, vectorized half2 stores.
// ---------------------------------------------------------------------------
__global__ void transpose_all(const float* __restrict__ Wo, __half* __restrict__ WoT,
                              const float* __restrict__ W1, __half* __restrict__ W1T,
                              const float* __restrict__ W2, __half* __restrict__ W2T) {
    __shared__ float t[32][33];
    int bid = blockIdx.x;
    const float* src;
    __half* dst;
    int R, C, ti;
    if (bid < 1024) {
        src = Wo; dst = WoT; R = D_; C = D_; ti = bid;
    } else if (bid < 5120) {
        src = W1; dst = W1T; R = D_; C = F_; ti = bid - 1024;
    } else {
        src = W2; dst = W2T; R = F_; C = D_; ti = bid - 5120;
    }
    int tilesX = C / 32;
    int r0 = (ti / tilesX) * 32, c0 = (ti % tilesX) * 32;
    int tid = threadIdx.x;
    int lx = tid & 31, ly = tid >> 5;
    for (int i = ly; i < 32; i += 8)
        t[i][lx] = src[(size_t)(r0 + i) * C + c0 + lx];
    __syncthreads();
    for (int wj = tid; wj < 32 * 16; wj += 256) {
        int i = wj >> 4, w = wj & 15;
        __half2 v = __floats2half2_rn(t[2 * w][i], t[2 * w + 1][i]);
        *(__half2*)&dst[(size_t)(c0 + i) * R + r0 + 2 * w] = v;
    }
}

// ---------------------------------------------------------------------------
// FP16 mma.sync GEMM.
// EPI: bit0 bias, bit1 relu, bit2 residual(fp32), bit3 fp16 out (else fp32).
// Split-K via gridDim.z only valid with EPI=0.
// ---------------------------------------------------------------------------
#define STRH 20
#define TILEU (128 * STRH)
#define STAGEU (2 * TILEU)
#define SMEM_GEMM (2 * STAGEU * 4)

template <int EPI>
__global__ __launch_bounds__(128, 3)
void mma_gemm_h(const __half* __restrict__ A, const __half* __restrict__ Bt,
                void* __restrict__ Cv, const float* __restrict__ bias,
                const float* __restrict__ res, int M, int N, int K) {
    extern __shared__ uint32_t smu[];
    int tid = threadIdx.x;
    int lane = tid & 31, warp = tid >> 5;
    int wm = warp & 1, wn = warp >> 1;
    int g = lane >> 2, tg = lane & 3;
    int bm = blockIdx.y * 128, bn = blockIdx.x * 128;

    int kspl = K / gridDim.z;
    int kOff = blockIdx.z * kspl;
    A += kOff;
    Bt += kOff;
    float* Cf = (float*)Cv + (size_t)blockIdx.z * M * N;
    __half* Ch = (__half*)Cv;

    float acc[4][8][4];
#pragma unroll
    for (int i = 0; i < 4; i++)
#pragma unroll
        for (int j = 0; j < 8; j++)
#pragma unroll
            for (int c = 0; c < 4; c++) acc[i][j][c] = 0.f;

    const int KT = kspl / 32;

    int pr = tid >> 2, pc = tid & 3;
    const __half* aSrc = A + (size_t)(bm + pr) * K + pc * 8;
    const __half* bSrc = Bt + (size_t)(bn + pr) * K + pc * 8;
    uint32_t smemBase = (uint32_t)__cvta_generic_to_shared(smu);
    uint32_t aDst0 = smemBase + (uint32_t)(pr * 80 + pc * 16);
    uint32_t bDst0 = smemBase + TILEU * 4 + (uint32_t)(pr * 80 + pc * 16);

    auto prefetch = [&](int stage) {
        uint32_t so = (uint32_t)(stage * STAGEU * 4);
#pragma unroll
        for (int q = 0; q < 4; q++) {
            uint32_t dst = aDst0 + so + (uint32_t)(q * 32 * 80);
            const __half* src = aSrc + (size_t)(q * 32) * K;
            asm volatile("cp.async.cg.shared.global [%0], [%1], 16;" :: "r"(dst), "l"(src));
        }
#pragma unroll
        for (int q = 0; q < 4; q++) {
            uint32_t dst = bDst0 + so + (uint32_t)(q * 32 * 80);
            const __half* src = bSrc + (size_t)(q * 32) * K;
            asm volatile("cp.async.cg.shared.global [%0], [%1], 16;" :: "r"(dst), "l"(src));
        }
        aSrc += 32;
        bSrc += 32;
    };

    prefetch(0);
    asm volatile("cp.async.commit_group;");

    for (int kt = 0; kt < KT; kt++) {
        if (kt + 1 < KT) prefetch((kt + 1) & 1);
        asm volatile("cp.async.commit_group;");
        asm volatile("cp.async.wait_group 1;");
        __syncthreads();

        const uint32_t* As = smu + (kt & 1) * STAGEU;
        const uint32_t* Bs = As + TILEU;
#pragma unroll
        for (int ks = 0; ks < 2; ks++) {
            int ku = ks * 8;
            uint32_t afr[4][4];
#pragma unroll
            for (int mi = 0; mi < 4; mi++) {
                int m = wm * 64 + mi * 16 + g;
                afr[mi][0] = As[m * STRH + ku + tg];
                afr[mi][1] = As[(m + 8) * STRH + ku + tg];
                afr[mi][2] = As[m * STRH + ku + tg + 4];
                afr[mi][3] = As[(m + 8) * STRH + ku + tg + 4];
            }
            uint32_t bfr[8][2];
#pragma unroll
            for (int ni = 0; ni < 8; ni++) {
                int n = wn * 64 + ni * 8 + g;
                bfr[ni][0] = Bs[n * STRH + ku + tg];
                bfr[ni][1] = Bs[n * STRH + ku + tg + 4];
            }
#pragma unroll
            for (int mi = 0; mi < 4; mi++)
#pragma unroll
                for (int ni = 0; ni < 8; ni++)
                    mma_f16(acc[mi][ni], afr[mi], bfr[ni]);
        }
        __syncthreads();
    }

#pragma unroll
    for (int mi = 0; mi < 4; mi++) {
#pragma unroll
        for (int rr = 0; rr < 2; rr++) {
            int row = bm + wm * 64 + mi * 16 + rr * 8 + g;
#pragma unroll
            for (int ni = 0; ni < 8; ni++) {
                int col = bn + wn * 64 + ni * 8 + tg * 2;
                float vx = acc[mi][ni][rr * 2 + 0];
                float vy = acc[mi][ni][rr * 2 + 1];
                if (EPI & 1) { vx += bias[col]; vy += bias[col + 1]; }
                if (EPI & 4) {
                    const float* rp = res + (size_t)row * N + col;
                    vx += rp[0]; vy += rp[1];
                }
                if (EPI & 2) { vx = fmaxf(vx, 0.f); vy = fmaxf(vy, 0.f); }
                if (EPI & 8) {
                    *(__half2*)&Ch[(size_t)row * N + col] = __floats2half2_rn(vx, vy);
                } else {
                    *(float2*)&Cf[(size_t)row * N + col] = make_float2(vx, vy);
                }
            }
        }
    }
}

// ---------------------------------------------------------------------------
// Fused attention per (b, h) — fp16 MMAs + register-resident softmax.
// ---------------------------------------------------------------------------
#define QH_STR 36
#define KH_STR 36
#define VT_STR 60
#define QH_OFF 0
#define KH_OFF (QH_OFF + 112 * QH_STR)
#define VT_OFF (KH_OFF + 112 * KH_STR)
#define ATT_U32 (VT_OFF + 64 * VT_STR)
#define ATT_SMEM (ATT_U32 * 4)   // 47616 bytes

__global__ __launch_bounds__(256)
void attention_kernel(const __half* __restrict__ QKV, __half* __restrict__ ctx) {
    extern __shared__ uint32_t su[];
    uint32_t* qh = su + QH_OFF;
    uint32_t* kh = su + KH_OFF;
    uint32_t* vt = su + VT_OFF;
    __half* vth = (__half*)vt;

    int bh = blockIdx.x;
    int b = bh / H_;
    int h = bh % H_;
    int tid = threadIdx.x;
    int lane = tid & 31, warp = tid >> 5;
    int g = lane >> 2, tg = lane & 3;

    for (int i = tid; i < 64 * VT_STR; i += 256) vt[i] = 0;
    __syncthreads();

    for (int i = tid; i < S_ * 16; i += 256) {
        int s = i >> 4, e4 = (i & 15) * 4;
        size_t off = ((size_t)(b * S_ + s)) * N_QKV + h * DEPTH_ + e4;
        qh[s * QH_STR + e4 / 2] = *(const uint32_t*)(QKV + off);
        qh[s * QH_STR + e4 / 2 + 1] = *(const uint32_t*)(QKV + off + 2);
        kh[s * KH_STR + e4 / 2] = *(const uint32_t*)(QKV + off + D_);
        kh[s * KH_STR + e4 / 2 + 1] = *(const uint32_t*)(QKV + off + D_ + 2);
        __half2 v01 = *(const __half2*)(QKV + off + 2 * D_);
        __half2 v23 = *(const __half2*)(QKV + off + 2 * D_ + 2);
        vth[(e4 + 0) * (VT_STR * 2) + s] = __low2half(v01);
        vth[(e4 + 1) * (VT_STR * 2) + s] = __high2half(v01);
        vth[(e4 + 2) * (VT_STR * 2) + s] = __low2half(v23);
        vth[(e4 + 3) * (VT_STR * 2) + s] = __high2half(v23);
    }
    __syncthreads();

    if (warp >= 7) return;

    float acc[13][4];
#pragma unroll
    for (int ni = 0; ni < 13; ni++)
#pragma unroll
        for (int c = 0; c < 4; c++) acc[ni][c] = 0.f;
    {
        int m = warp * 16 + g;
#pragma unroll
        for (int ks = 0; ks < 4; ks++) {
            int ku = ks * 8;
            uint32_t a[4];
            a[0] = qh[m * QH_STR + ku + tg];
            a[1] = qh[(m + 8) * QH_STR + ku + tg];
            a[2] = qh[m * QH_STR + ku + tg + 4];
            a[3] = qh[(m + 8) * QH_STR + ku + tg + 4];
#pragma unroll
            for (int ni = 0; ni < 13; ni++) {
                int n = ni * 8 + g;
                uint32_t bf[2];
                bf[0] = kh[n * KH_STR + ku + tg];
                bf[1] = kh[n * KH_STR + ku + tg + 4];
                mma_f16(acc[ni], a, bf);
            }
        }
    }

    const float scale = 0.125f;
#pragma unroll
    for (int rr = 0; rr < 2; rr++) {
        float m = -1e30f;
#pragma unroll
        for (int ni = 0; ni < 13; ni++)
#pragma unroll
            for (int j = 0; j < 2; j++) {
                int col = ni * 8 + 2 * tg + j;
                if (col < S_) m = fmaxf(m, acc[ni][rr * 2 + j] * scale);
            }
        m = fmaxf(m, __shfl_xor_sync(0xffffffffu, m, 1));
        m = fmaxf(m, __shfl_xor_sync(0xffffffffu, m, 2));
        float sum = 0.f;
#pragma unroll
        for (int ni = 0; ni < 13; ni++)
#pragma unroll
            for (int j = 0; j < 2; j++) {
                int col = ni * 8 + 2 * tg + j;
                float e = 0.f;
                if (col < S_) e = __expf(acc[ni][rr * 2 + j] * scale - m);
                acc[ni][rr * 2 + j] = e;
                sum += e;
            }
        sum += __shfl_xor_sync(0xffffffffu, sum, 1);
        sum += __shfl_xor_sync(0xffffffffu, sum, 2);
        float inv = 1.f / sum;
#pragma unroll
        for (int ni = 0; ni < 13; ni++) {
            acc[ni][rr * 2 + 0] *= inv;
            acc[ni][rr * 2 + 1] *= inv;
        }
    }

    float oacc[8][4];
#pragma unroll
    for (int ni = 0; ni < 8; ni++)
#pragma unroll
        for (int c = 0; c < 4; c++) oacc[ni][c] = 0.f;
#pragma unroll
    for (int ks = 0; ks < 7; ks++) {
        uint32_t a[4];
        __half2 h0 = __floats2half2_rn(acc[2 * ks][0], acc[2 * ks][1]);
        __half2 h1 = __floats2half2_rn(acc[2 * ks][2], acc[2 * ks][3]);
        a[0] = *(uint32_t*)&h0;
        a[1] = *(uint32_t*)&h1;
        if (ks < 6) {
            __half2 h2 = __floats2half2_rn(acc[2 * ks + 1][0], acc[2 * ks + 1][1]);
            __half2 h3 = __floats2half2_rn(acc[2 * ks + 1][2], acc[2 * ks + 1][3]);
            a[2] = *(uint32_t*)&h2;
            a[3] = *(uint32_t*)&h3;
        } else {
            a[2] = 0;
            a[3] = 0;
        }
        int ku = ks * 8;
#pragma unroll
        for (int ni = 0; ni < 8; ni++) {
            int n = ni * 8 + g;
            uint32_t bf[2];
            bf[0] = vt[n * VT_STR + ku + tg];
            bf[1] = vt[n * VT_STR + ku + tg + 4];
            mma_f16(oacc[ni], a, bf);
        }
    }

    const size_t cbase = (size_t)b * S_ * D_ + (size_t)h * DEPTH_;
#pragma unroll
    for (int ni = 0; ni < 8; ni++)
#pragma unroll
        for (int rr = 0; rr < 2; rr++) {
            int row = warp * 16 + rr * 8 + g;
            if (row < S_) {
                int col = ni * 8 + tg * 2;
                *(__half2*)&ctx[cbase + (size_t)row * D_ + col] =
                    __floats2half2_rn(oacc[ni][rr * 2], oacc[ni][rr * 2 + 1]);
            }
        }
}

// ---------------------------------------------------------------------------
// LayerNorm variants. SPLIT: in = p0+p1+bias+res; else in = p0 only.
// ---------------------------------------------------------------------------
template <bool SPLIT, bool HALF2>
__global__ __launch_bounds__(256)
void lnred_kernel(const float* __restrict__ p0, const float* __restrict__ p1,
                  const float* __restrict__ bias, const float* __restrict__ res,
                  const float* __restrict__ gamma, const float* __restrict__ beta,
                  float* __restrict__ out, __half* __restrict__ out_h) {
    int row = blockIdx.x;
    size_t base = (size_t)row * D_;
    int tid = threadIdx.x;

    float vals[4];
    float sum = 0.f, sq = 0.f;
#pragma unroll
    for (int r = 0; r < 4; r++) {
        int d = tid + r * 256;
        float v;
        if (SPLIT) v = p0[base + d] + p1[base + d] + bias[d] + res[base + d];
        else       v = p0[base + d];
        vals[r] = v;
        sum += v;
        sq += v * v;
    }
#pragma unroll
    for (int off = 16; off > 0; off >>= 1) {
        sum += __shfl_xor_sync(0xffffffffu, sum, off);
        sq += __shfl_xor_sync(0xffffffffu, sq, off);
    }
    __shared__ float s1[8], s2[8];
    int wid = tid >> 5, lid = tid & 31;
    if (lid == 0) { s1[wid] = sum; s2[wid] = sq; }
    __syncthreads();
    if (wid == 0) {
        sum = (lid < 8) ? s1[lid] : 0.f;
        sq = (lid < 8) ? s2[lid] : 0.f;
#pragma unroll
        for (int off = 4; off > 0; off >>= 1) {
            sum += __shfl_xor_sync(0xffffffffu, sum, off);
            sq += __shfl_xor_sync(0xffffffffu, sq, off);
        }
        if (lid == 0) { s1[0] = sum; s2[0] = sq; }
    }
    __syncthreads();
    float mean = s1[0] * (1.0f / D_);
    float var = s2[0] * (1.0f / D_) - mean * mean;
    float inv = rsqrtf(var + EPS_);
#pragma unroll
    for (int r = 0; r < 4; r++) {
        int d = tid + r * 256;
        float o = gamma[d] * ((vals[r] - mean) * inv) + beta[d];
        out[base + d] = o;
        if (HALF2) out_h[base + d] = __float2half_rn(o);
    }
}

// ---------------------------------------------------------------------------
// Launch
// ---------------------------------------------------------------------------
extern "C" void kernel_launch(void* const* d_in, const int* in_sizes, int n_in,
                              void* d_out, int out_size) {
    const int* tokens = (const int*)d_in[0];
    const float* emb = (const float*)d_in[1];
    const float* Wq = (const float*)d_in[2];
    const float* bq = (const float*)d_in[3];
    const float* Wk = (const float*)d_in[4];
    const float* bk = (const float*)d_in[5];
    const float* Wv = (const float*)d_in[6];
    const float* bv = (const float*)d_in[7];
    const float* Wo = (const float*)d_in[8];
    const float* bo = (const float*)d_in[9];
    const float* W1 = (const float*)d_in[10];
    const float* b1 = (const float*)d_in[11];
    const float* W2 = (const float*)d_in[12];
    const float* b2 = (const float*)d_in[13];
    const float* gamma1 = (const float*)d_in[14];
    const float* beta1 = (const float*)d_in[15];
    const float* gamma2 = (const float*)d_in[16];
    const float* beta2 = (const float*)d_in[17];
    float* out = (float*)d_out;

    float *pe, *x, *bqkv, *t1, *x1;
    __half *xh, *WqkvTh, *WoTh, *W1Th, *W2Th, *QKVh, *ctxh, *x1h, *ffhh;
    cudaGetSymbolAddress((void**)&pe, g_pe);
    cudaGetSymbolAddress((void**)&x, g_x);
    cudaGetSymbolAddress((void**)&xh, g_xh);
    cudaGetSymbolAddress((void**)&WqkvTh, g_WqkvTh);
    cudaGetSymbolAddress((void**)&bqkv, g_bqkv);
    cudaGetSymbolAddress((void**)&WoTh, g_WoTh);
    cudaGetSymbolAddress((void**)&W1Th, g_W1Th);
    cudaGetSymbolAddress((void**)&W2Th, g_W2Th);
    cudaGetSymbolAddress((void**)&QKVh, g_QKVh);
    cudaGetSymbolAddress((void**)&ctxh, g_ctxh);
    cudaGetSymbolAddress((void**)&t1, g_t1);
    cudaGetSymbolAddress((void**)&x1, g_x1);
    cudaGetSymbolAddress((void**)&x1h, g_x1h);
    cudaGetSymbolAddress((void**)&ffhh, g_ffhh);

    cudaFuncSetAttribute(attention_kernel,
                         cudaFuncAttributeMaxDynamicSharedMemorySize, ATT_SMEM);
    cudaFuncSetAttribute(mma_gemm_h<0>,
                         cudaFuncAttributeMaxDynamicSharedMemorySize, SMEM_GEMM);
    cudaFuncSetAttribute(mma_gemm_h<5>,
                         cudaFuncAttributeMaxDynamicSharedMemorySize, SMEM_GEMM);
    cudaFuncSetAttribute(mma_gemm_h<9>,
                         cudaFuncAttributeMaxDynamicSharedMemorySize, SMEM_GEMM);
    cudaFuncSetAttribute(mma_gemm_h<11>,
                         cudaFuncAttributeMaxDynamicSharedMemorySize, SMEM_GEMM);

    // 0-1. positional encoding + embedding (+ bias concat folded in)
    pe_kernel<<<(S_ * D_ + 255) / 256, 256>>>(pe);
    embed_kernel<<<(BS_ * D_ / 4 + 255) / 256, 256>>>(tokens, emb, pe, x, xh,
                                                      bq, bk, bv, bqkv);

    // 2-3. weight prep (merged transposes, vectorized half2 stores)
    qkvT_kernel<<<dim3(2, 32, 48), dim3(32, 8)>>>(Wq, Wk, Wv, WqkvTh);
    transpose_all<<<9216, 256>>>(Wo, WoTh, W1, W1Th, W2, W2Th);

    // 4. fused QKV projection (bias + fp16 output)
    mma_gemm_h<9><<<dim3(N_QKV / 128, BS_ / 128), 128, SMEM_GEMM>>>(
        xh, WqkvTh, QKVh, bqkv, nullptr, BS_, N_QKV, D_);

    // 5. attention (fp16 MMA, register softmax)
    attention_kernel<<<B_ * H_, 256, ATT_SMEM>>>(QKVh, ctxh);

    // 6-7. output projection (unsplit, bias+residual fused, fp32 out) + LN1
    mma_gemm_h<5><<<dim3(D_ / 128, BS_ / 128), 128, SMEM_GEMM>>>(
        ctxh, WoTh, t1, bo, x, BS_, D_, D_);
    lnred_kernel<false, true><<<BS_, 256>>>(t1, nullptr, nullptr, nullptr,
                                            gamma1, beta1, x1, x1h);

    // 8-9. FFN: W1 (bias+relu+fp16 out), W2 (split-K 2)
    mma_gemm_h<11><<<dim3(F_ / 128, BS_ / 128), 128, SMEM_GEMM>>>(
        x1h, W1Th, ffhh, b1, nullptr, BS_, F_, D_);
    mma_gemm_h<0><<<dim3(D_ / 128, BS_ / 128, 2), 128, SMEM_GEMM>>>(
        ffhh, W2Th, t1, nullptr, nullptr, BS_, D_, F_);

    // 10. fused reduce + LN2 -> output
    lnred_kernel<true, false><<<BS_, 256>>>(t1, t1 + (size_t)BS_ * D_, b2, x1,
                                            gamma2, beta2, out, nullptr);
}

// round 17
// speedup vs baseline: 1.0048x; 1.0048x over previous
#include <cuda_runtime.h>
#include <cuda_fp16.h>
#include <math.h>
#include <stdint.h>

// Problem constants
#define B_ 64
#define S_ 100
#define D_ 1024
#define H_ 16
#define F_ 4096
#define DEPTH_ 64
#define BS_ (B_ * S_)          // 6400
#define N_QKV 3072
#define EPS_ 1e-6f

// ---------------------------------------------------------------------------
// Scratch (device globals; no allocations allowed)
// ---------------------------------------------------------------------------
__device__ float g_pe[S_ * D_];
__device__ float g_x[BS_ * D_];          // fp32 residual
__device__ __half g_xh[BS_ * D_];        // fp16 GEMM A operand
__device__ __half g_WqkvTh[N_QKV * D_];  // [N,K] fp16
__device__ float g_bqkv[N_QKV];
__device__ __half g_WoTh[D_ * D_];       // [N,K] fp16
__device__ __half g_W1Th[F_ * D_];       // [N,K] fp16
__device__ __half g_W2Th[D_ * F_];       // [N,K] fp16
__device__ __half g_QKVh[BS_ * N_QKV];   // fp16 QKV
__device__ __half g_ctxh[BS_ * D_];      // fp16 attention output
__device__ float g_t1[2 * BS_ * D_];     // split-K fp32 partials / pre-LN buffer
__device__ float g_x1[BS_ * D_];         // fp32 residual
__device__ __half g_x1h[BS_ * D_];       // fp16 twin
__device__ __half g_ffhh[BS_ * F_];      // fp16 relu output

__device__ __forceinline__ void mma_f16(float* d, const uint32_t* a, const uint32_t* b) {
    asm volatile(
        "mma.sync.aligned.m16n8k16.row.col.f32.f16.f16.f32 "
        "{%0,%1,%2,%3}, {%4,%5,%6,%7}, {%8,%9}, {%0,%1,%2,%3};\n"
        : "+f"(d[0]), "+f"(d[1]), "+f"(d[2]), "+f"(d[3])
        : "r"(a[0]), "r"(a[1]), "r"(a[2]), "r"(a[3]), "r"(b[0]), "r"(b[1]));
}

__device__ __forceinline__ void ldsm4(uint32_t* r, uint32_t addr) {
    asm volatile("ldmatrix.sync.aligned.m8n8.x4.shared.b16 {%0,%1,%2,%3}, [%4];"
                 : "=r"(r[0]), "=r"(r[1]), "=r"(r[2]), "=r"(r[3]) : "r"(addr));
}

// ---------------------------------------------------------------------------
// Positional encoding (fp32). log2(10000) = 13.287712379549449.
// ---------------------------------------------------------------------------
__global__ void pe_kernel(float* __restrict__ pe) {
    int idx = blockIdx.x * blockDim.x + threadIdx.x;
    if (idx >= S_ * D_) return;
    int s = idx / D_;
    int d = idx % D_;
    int k2 = d & ~1;
    float div = exp2f((float)k2 * (13.2877123795494f / (float)D_));
    float arg = (float)s / div;
    pe[idx] = (d & 1) ? cosf(arg) : sinf(arg);
}

// ---------------------------------------------------------------------------
// Embedding gather + positional add; fp32 x, fp16 xh. Also concats QKV bias.
// ---------------------------------------------------------------------------
__global__ void embed_kernel(const int* __restrict__ tokens,
                             const float* __restrict__ emb,
                             const float* __restrict__ pe,
                             float* __restrict__ x, __half* __restrict__ xh,
                             const float* __restrict__ bq, const float* __restrict__ bk,
                             const float* __restrict__ bv, float* __restrict__ bqkv) {
    int idx = blockIdx.x * blockDim.x + threadIdx.x;
    if (idx < N_QKV) {
        int which = idx / D_;
        int n = idx % D_;
        const float* bb = (which == 0) ? bq : ((which == 1) ? bk : bv);
        bqkv[idx] = bb[n];
    }
    if (idx >= BS_ * D_ / 4) return;
    int row = idx / (D_ / 4);
    int c4 = idx % (D_ / 4);
    int tok = tokens[row];
    float4 e = ((const float4*)(emb + (size_t)tok * D_))[c4];
    float4 p = ((const float4*)(pe + (size_t)(row % S_) * D_))[c4];
    float4 o;
    o.x = e.x + p.x; o.y = e.y + p.y; o.z = e.z + p.z; o.w = e.w + p.w;
    ((float4*)x)[idx] = o;
    ((__half2*)xh)[idx * 2 + 0] = __floats2half2_rn(o.x, o.y);
    ((__half2*)xh)[idx * 2 + 1] = __floats2half2_rn(o.z, o.w);
}

// ---------------------------------------------------------------------------
// QKV weight transpose: W{q,k,v}[H,D,64] -> WqkvTh[3072, 1024] fp16 ([N,K])
// ---------------------------------------------------------------------------
__global__ void qkvT_kernel(const float* __restrict__ Wq, const float* __restrict__ Wk,
                            const float* __restrict__ Wv, __half* __restrict__ Wt) {
    __shared__ float t[32][33];
    int z = blockIdx.z;
    int which = z / H_, h = z % H_;
    const float* W = (which == 0) ? Wq : ((which == 1) ? Wk : Wv);
    const float* src = W + (size_t)h * D_ * DEPTH_;
    int e0 = blockIdx.x * 32, d0 = blockIdx.y * 32;
    int tx = threadIdx.x, ty = threadIdx.y;
    for (int i = ty; i < 32; i += 8)
        t[i][tx] = src[(size_t)(d0 + i) * DEPTH_ + e0 + tx];
    __syncthreads();
    __half* dst = Wt + ((size_t)which * D_ + h * DEPTH_) * D_;
    for (int i = ty; i < 32; i += 8)
        dst[(size_t)(e0 + i) * D_ + d0 + tx] = __float2half_rn(t[tx][i]);
}

// ---------------------------------------------------------------------------
// Merged transpose of Wo, W1, W2 -> fp16, half2 stores.
// ---------------------------------------------------------------------------
__global__ void transpose_all(const float* __restrict__ Wo, __half* __restrict__ WoT,
                              const float* __restrict__ W1, __half* __restrict__ W1T,
                              const float* __restrict__ W2, __half* __restrict__ W2T) {
    __shared__ float t[32][33];
    int bid = blockIdx.x;
    const float* src;
    __half* dst;
    int R, C, ti;
    if (bid < 1024) {
        src = Wo; dst = WoT; R = D_; C = D_; ti = bid;
    } else if (bid < 5120) {
        src = W1; dst = W1T; R = D_; C = F_; ti = bid - 1024;
    } else {
        src = W2; dst = W2T; R = F_; C = D_; ti = bid - 5120;
    }
    int tilesX = C / 32;
    int r0 = (ti / tilesX) * 32, c0 = (ti % tilesX) * 32;
    int tid = threadIdx.x;
    int lx = tid & 31, ly = tid >> 5;
    for (int i = ly; i < 32; i += 8)
        t[i][lx] = src[(size_t)(r0 + i) * C + c0 + lx];
    __syncthreads();
    for (int wj = tid; wj < 32 * 16; wj += 256) {
        int i = wj >> 4, w = wj & 15;
        __half2 v = __floats2half2_rn(t[2 * w][i], t[2 * w + 1][i]);
        *(__half2*)&dst[(size_t)(c0 + i) * R + r0 + 2 * w] = v;
    }
}

// ---------------------------------------------------------------------------
// FP16 mma.sync GEMM with ldmatrix fragment loads.
// Tiles [128 rows][32 halves], u32 stride 20 (80 B rows).
// ldmatrix bank check: 8-lane phase banks 20*l mod 32 = all-distinct,
// 16B accesses tile all 32 banks exactly once. Conflict-free.
// EPI: bit0 bias, bit1 relu, bit2 residual(fp32), bit3 fp16 out (else fp32).
// Split-K via gridDim.z only valid with EPI=0.
// ---------------------------------------------------------------------------
#define STRH 20
#define TILEU (128 * STRH)
#define STAGEU (2 * TILEU)
#define SMEM_GEMM (2 * STAGEU * 4)

template <int EPI>
__global__ __launch_bounds__(128, 3)
void mma_gemm_h(const __half* __restrict__ A, const __half* __restrict__ Bt,
                void* __restrict__ Cv, const float* __restrict__ bias,
                const float* __restrict__ res, int M, int N, int K) {
    extern __shared__ uint32_t smu[];
    int tid = threadIdx.x;
    int lane = tid & 31, warp = tid >> 5;
    int wm = warp & 1, wn = warp >> 1;
    int g = lane >> 2, tg = lane & 3;
    int bm = blockIdx.y * 128, bn = blockIdx.x * 128;

    int kspl = K / gridDim.z;
    int kOff = blockIdx.z * kspl;
    A += kOff;
    Bt += kOff;
    float* Cf = (float*)Cv + (size_t)blockIdx.z * M * N;
    __half* Ch = (__half*)Cv;

    float acc[4][8][4];
#pragma unroll
    for (int i = 0; i < 4; i++)
#pragma unroll
        for (int j = 0; j < 8; j++)
#pragma unroll
            for (int c = 0; c < 4; c++) acc[i][j][c] = 0.f;

    const int KT = kspl / 32;

    int pr = tid >> 2, pc = tid & 3;
    const __half* aSrc = A + (size_t)(bm + pr) * K + pc * 8;
    const __half* bSrc = Bt + (size_t)(bn + pr) * K + pc * 8;
    uint32_t smemBase = (uint32_t)__cvta_generic_to_shared(smu);
    uint32_t aDst0 = smemBase + (uint32_t)(pr * 80 + pc * 16);
    uint32_t bDst0 = smemBase + TILEU * 4 + (uint32_t)(pr * 80 + pc * 16);

    auto prefetch = [&](int stage) {
        uint32_t so = (uint32_t)(stage * STAGEU * 4);
#pragma unroll
        for (int q = 0; q < 4; q++) {
            uint32_t dst = aDst0 + so + (uint32_t)(q * 32 * 80);
            const __half* src = aSrc + (size_t)(q * 32) * K;
            asm volatile("cp.async.cg.shared.global [%0], [%1], 16;" :: "r"(dst), "l"(src));
        }
#pragma unroll
        for (int q = 0; q < 4; q++) {
            uint32_t dst = bDst0 + so + (uint32_t)(q * 32 * 80);
            const __half* src = bSrc + (size_t)(q * 32) * K;
            asm volatile("cp.async.cg.shared.global [%0], [%1], 16;" :: "r"(dst), "l"(src));
        }
        aSrc += 32;
        bSrc += 32;
    };

    // ldmatrix per-lane offset (bytes): row = (lane>>3 & 1)*8 + (lane&7),
    // col16 = (lane>>4)*16.
    uint32_t lmOff = (uint32_t)((((lane >> 3) & 1) * 8 + (lane & 7)) * 80 +
                                (lane >> 4) * 16);

    prefetch(0);
    asm volatile("cp.async.commit_group;");

    for (int kt = 0; kt < KT; kt++) {
        if (kt + 1 < KT) prefetch((kt + 1) & 1);
        asm volatile("cp.async.commit_group;");
        asm volatile("cp.async.wait_group 1;");
        __syncthreads();

        uint32_t sA = smemBase + (uint32_t)((kt & 1) * STAGEU * 4);
        uint32_t sB = sA + TILEU * 4;
#pragma unroll
        for (int ks = 0; ks < 2; ks++) {
            uint32_t kb = (uint32_t)(ks * 32);   // 16 halves = 32 bytes
            uint32_t afr[4][4];
#pragma unroll
            for (int mi = 0; mi < 4; mi++)
                ldsm4(afr[mi], sA + (uint32_t)((wm * 64 + mi * 16) * 80) + lmOff + kb);
            uint32_t bfr[8][2];
#pragma unroll
            for (int nj = 0; nj < 4; nj++) {
                uint32_t t[4];
                ldsm4(t, sB + (uint32_t)((wn * 64 + nj * 16) * 80) + lmOff + kb);
                bfr[2 * nj][0] = t[0];
                bfr[2 * nj + 1][0] = t[1];
                bfr[2 * nj][1] = t[2];
                bfr[2 * nj + 1][1] = t[3];
            }
#pragma unroll
            for (int mi = 0; mi < 4; mi++)
#pragma unroll
                for (int ni = 0; ni < 8; ni++)
                    mma_f16(acc[mi][ni], afr[mi], bfr[ni]);
        }
        __syncthreads();
    }

#pragma unroll
    for (int mi = 0; mi < 4; mi++) {
#pragma unroll
        for (int rr = 0; rr < 2; rr++) {
            int row = bm + wm * 64 + mi * 16 + rr * 8 + g;
#pragma unroll
            for (int ni = 0; ni < 8; ni++) {
                int col = bn + wn * 64 + ni * 8 + tg * 2;
                float vx = acc[mi][ni][rr * 2 + 0];
                float vy = acc[mi][ni][rr * 2 + 1];
                if (EPI & 1) { vx += bias[col]; vy += bias[col + 1]; }
                if (EPI & 4) {
                    const float* rp = res + (size_t)row * N + col;
                    vx += rp[0]; vy += rp[1];
                }
                if (EPI & 2) { vx = fmaxf(vx, 0.f); vy = fmaxf(vy, 0.f); }
                if (EPI & 8) {
                    *(__half2*)&Ch[(size_t)row * N + col] = __floats2half2_rn(vx, vy);
                } else {
                    *(float2*)&Cf[(size_t)row * N + col] = make_float2(vx, vy);
                }
            }
        }
    }
}

// ---------------------------------------------------------------------------
// Fused attention per (b, h) — fp16 MMAs + register-resident softmax.
// ---------------------------------------------------------------------------
#define QH_STR 36
#define KH_STR 36
#define VT_STR 60
#define QH_OFF 0
#define KH_OFF (QH_OFF + 112 * QH_STR)
#define VT_OFF (KH_OFF + 112 * KH_STR)
#define ATT_U32 (VT_OFF + 64 * VT_STR)
#define ATT_SMEM (ATT_U32 * 4)   // 47616 bytes

__global__ __launch_bounds__(256)
void attention_kernel(const __half* __restrict__ QKV, __half* __restrict__ ctx) {
    extern __shared__ uint32_t su[];
    uint32_t* qh = su + QH_OFF;
    uint32_t* kh = su + KH_OFF;
    uint32_t* vt = su + VT_OFF;
    __half* vth = (__half*)vt;

    int bh = blockIdx.x;
    int b = bh / H_;
    int h = bh % H_;
    int tid = threadIdx.x;
    int lane = tid & 31, warp = tid >> 5;
    int g = lane >> 2, tg = lane & 3;

    for (int i = tid; i < 64 * VT_STR; i += 256) vt[i] = 0;
    __syncthreads();

    for (int i = tid; i < S_ * 16; i += 256) {
        int s = i >> 4, e4 = (i & 15) * 4;
        size_t off = ((size_t)(b * S_ + s)) * N_QKV + h * DEPTH_ + e4;
        qh[s * QH_STR + e4 / 2] = *(const uint32_t*)(QKV + off);
        qh[s * QH_STR + e4 / 2 + 1] = *(const uint32_t*)(QKV + off + 2);
        kh[s * KH_STR + e4 / 2] = *(const uint32_t*)(QKV + off + D_);
        kh[s * KH_STR + e4 / 2 + 1] = *(const uint32_t*)(QKV + off + D_ + 2);
        __half2 v01 = *(const __half2*)(QKV + off + 2 * D_);
        __half2 v23 = *(const __half2*)(QKV + off + 2 * D_ + 2);
        vth[(e4 + 0) * (VT_STR * 2) + s] = __low2half(v01);
        vth[(e4 + 1) * (VT_STR * 2) + s] = __high2half(v01);
        vth[(e4 + 2) * (VT_STR * 2) + s] = __low2half(v23);
        vth[(e4 + 3) * (VT_STR * 2) + s] = __high2half(v23);
    }
    __syncthreads();

    if (warp >= 7) return;

    float acc[13][4];
#pragma unroll
    for (int ni = 0; ni < 13; ni++)
#pragma unroll
        for (int c = 0; c < 4; c++) acc[ni][c] = 0.f;
    {
        int m = warp * 16 + g;
#pragma unroll
        for (int ks = 0; ks < 4; ks++) {
            int ku = ks * 8;
            uint32_t a[4];
            a[0] = qh[m * QH_STR + ku + tg];
            a[1] = qh[(m + 8) * QH_STR + ku + tg];
            a[2] = qh[m * QH_STR + ku + tg + 4];
            a[3] = qh[(m + 8) * QH_STR + ku + tg + 4];
#pragma unroll
            for (int ni = 0; ni < 13; ni++) {
                int n = ni * 8 + g;
                uint32_t bf[2];
                bf[0] = kh[n * KH_STR + ku + tg];
                bf[1] = kh[n * KH_STR + ku + tg + 4];
                mma_f16(acc[ni], a, bf);
            }
        }
    }

    const float scale = 0.125f;
#pragma unroll
    for (int rr = 0; rr < 2; rr++) {
        float m = -1e30f;
#pragma unroll
        for (int ni = 0; ni < 13; ni++)
#pragma unroll
            for (int j = 0; j < 2; j++) {
                int col = ni * 8 + 2 * tg + j;
                if (col < S_) m = fmaxf(m, acc[ni][rr * 2 + j] * scale);
            }
        m = fmaxf(m, __shfl_xor_sync(0xffffffffu, m, 1));
        m = fmaxf(m, __shfl_xor_sync(0xffffffffu, m, 2));
        float sum = 0.f;
#pragma unroll
        for (int ni = 0; ni < 13; ni++)
#pragma unroll
            for (int j = 0; j < 2; j++) {
                int col = ni * 8 + 2 * tg + j;
                float e = 0.f;
                if (col < S_) e = __expf(acc[ni][rr * 2 + j] * scale - m);
                acc[ni][rr * 2 + j] = e;
                sum += e;
            }
        sum += __shfl_xor_sync(0xffffffffu, sum, 1);
        sum += __shfl_xor_sync(0xffffffffu, sum, 2);
        float inv = 1.f / sum;
#pragma unroll
        for (int ni = 0; ni < 13; ni++) {
            acc[ni][rr * 2 + 0] *= inv;
            acc[ni][rr * 2 + 1] *= inv;
        }
    }

    float oacc[8][4];
#pragma unroll
    for (int ni = 0; ni < 8; ni++)
#pragma unroll
        for (int c = 0; c < 4; c++) oacc[ni][c] = 0.f;
#pragma unroll
    for (int ks = 0; ks < 7; ks++) {
        uint32_t a[4];
        __half2 h0 = __floats2half2_rn(acc[2 * ks][0], acc[2 * ks][1]);
        __half2 h1 = __floats2half2_rn(acc[2 * ks][2], acc[2 * ks][3]);
        a[0] = *(uint32_t*)&h0;
        a[1] = *(uint32_t*)&h1;
        if (ks < 6) {
            __half2 h2 = __floats2half2_rn(acc[2 * ks + 1][0], acc[2 * ks + 1][1]);
            __half2 h3 = __floats2half2_rn(acc[2 * ks + 1][2], acc[2 * ks + 1][3]);
            a[2] = *(uint32_t*)&h2;
            a[3] = *(uint32_t*)&h3;
        } else {
            a[2] = 0;
            a[3] = 0;
        }
        int ku = ks * 8;
#pragma unroll
        for (int ni = 0; ni < 8; ni++) {
            int n = ni * 8 + g;
            uint32_t bf[2];
            bf[0] = vt[n * VT_STR + ku + tg];
            bf[1] = vt[n * VT_STR + ku + tg + 4];
            mma_f16(oacc[ni], a, bf);
        }
    }

    const size_t cbase = (size_t)b * S_ * D_ + (size_t)h * DEPTH_;
#pragma unroll
    for (int ni = 0; ni < 8; ni++)
#pragma unroll
        for (int rr = 0; rr < 2; rr++) {
            int row = warp * 16 + rr * 8 + g;
            if (row < S_) {
                int col = ni * 8 + tg * 2;
                *(__half2*)&ctx[cbase + (size_t)row * D_ + col] =
                    __floats2half2_rn(oacc[ni][rr * 2], oacc[ni][rr * 2 + 1]);
            }
        }
}

// ---------------------------------------------------------------------------
// LayerNorm variants. SPLIT: in = p0+p1+bias+res; else in = p0 only.
// ---------------------------------------------------------------------------
template <bool SPLIT, bool HALF2>
__global__ __launch_bounds__(256)
void lnred_kernel(const float* __restrict__ p0, const float* __restrict__ p1,
                  const float* __restrict__ bias, const float* __restrict__ res,
                  const float* __restrict__ gamma, const float* __restrict__ beta,
                  float* __restrict__ out, __half* __restrict__ out_h) {
    int row = blockIdx.x;
    size_t base = (size_t)row * D_;
    int tid = threadIdx.x;

    float vals[4];
    float sum = 0.f, sq = 0.f;
#pragma unroll
    for (int r = 0; r < 4; r++) {
        int d = tid + r * 256;
        float v;
        if (SPLIT) v = p0[base + d] + p1[base + d] + bias[d] + res[base + d];
        else       v = p0[base + d];
        vals[r] = v;
        sum += v;
        sq += v * v;
    }
#pragma unroll
    for (int off = 16; off > 0; off >>= 1) {
        sum += __shfl_xor_sync(0xffffffffu, sum, off);
        sq += __shfl_xor_sync(0xffffffffu, sq, off);
    }
    __shared__ float s1[8], s2[8];
    int wid = tid >> 5, lid = tid & 31;
    if (lid == 0) { s1[wid] = sum; s2[wid] = sq; }
    __syncthreads();
    if (wid == 0) {
        sum = (lid < 8) ? s1[lid] : 0.f;
        sq = (lid < 8) ? s2[lid] : 0.f;
#pragma unroll
        for (int off = 4; off > 0; off >>= 1) {
            sum += __shfl_xor_sync(0xffffffffu, sum, off);
            sq += __shfl_xor_sync(0xffffffffu, sq, off);
        }
        if (lid == 0) { s1[0] = sum; s2[0] = sq; }
    }
    __syncthreads();
    float mean = s1[0] * (1.0f / D_);
    float var = s2[0] * (1.0f / D_) - mean * mean;
    float inv = rsqrtf(var + EPS_);
#pragma unroll
    for (int r = 0; r < 4; r++) {
        int d = tid + r * 256;
        float o = gamma[d] * ((vals[r] - mean) * inv) + beta[d];
        out[base + d] = o;
        if (HALF2) out_h[base + d] = __float2half_rn(o);
    }
}

// ---------------------------------------------------------------------------
// Launch
// ---------------------------------------------------------------------------
extern "C" void kernel_launch(void* const* d_in, const int* in_sizes, int n_in,
                              void* d_out, int out_size) {
    const int* tokens = (const int*)d_in[0];
    const float* emb = (const float*)d_in[1];
    const float* Wq = (const float*)d_in[2];
    const float* bq = (const float*)d_in[3];
    const float* Wk = (const float*)d_in[4];
    const float* bk = (const float*)d_in[5];
    const float* Wv = (const float*)d_in[6];
    const float* bv = (const float*)d_in[7];
    const float* Wo = (const float*)d_in[8];
    const float* bo = (const float*)d_in[9];
    const float* W1 = (const float*)d_in[10];
    const float* b1 = (const float*)d_in[11];
    const float* W2 = (const float*)d_in[12];
    const float* b2 = (const float*)d_in[13];
    const float* gamma1 = (const float*)d_in[14];
    const float* beta1 = (const float*)d_in[15];
    const float* gamma2 = (const float*)d_in[16];
    const float* beta2 = (const float*)d_in[17];
    float* out = (float*)d_out;

    float *pe, *x, *bqkv, *t1, *x1;
    __half *xh, *WqkvTh, *WoTh, *W1Th, *W2Th, *QKVh, *ctxh, *x1h, *ffhh;
    cudaGetSymbolAddress((void**)&pe, g_pe);
    cudaGetSymbolAddress((void**)&x, g_x);
    cudaGetSymbolAddress((void**)&xh, g_xh);
    cudaGetSymbolAddress((void**)&WqkvTh, g_WqkvTh);
    cudaGetSymbolAddress((void**)&bqkv, g_bqkv);
    cudaGetSymbolAddress((void**)&WoTh, g_WoTh);
    cudaGetSymbolAddress((void**)&W1Th, g_W1Th);
    cudaGetSymbolAddress((void**)&W2Th, g_W2Th);
    cudaGetSymbolAddress((void**)&QKVh, g_QKVh);
    cudaGetSymbolAddress((void**)&ctxh, g_ctxh);
    cudaGetSymbolAddress((void**)&t1, g_t1);
    cudaGetSymbolAddress((void**)&x1, g_x1);
    cudaGetSymbolAddress((void**)&x1h, g_x1h);
    cudaGetSymbolAddress((void**)&ffhh, g_ffhh);

    cudaFuncSetAttribute(attention_kernel,
                         cudaFuncAttributeMaxDynamicSharedMemorySize, ATT_SMEM);
    cudaFuncSetAttribute(mma_gemm_h<0>,
                         cudaFuncAttributeMaxDynamicSharedMemorySize, SMEM_GEMM);
    cudaFuncSetAttribute(mma_gemm_h<5>,
                         cudaFuncAttributeMaxDynamicSharedMemorySize, SMEM_GEMM);
    cudaFuncSetAttribute(mma_gemm_h<9>,
                         cudaFuncAttributeMaxDynamicSharedMemorySize, SMEM_GEMM);
    cudaFuncSetAttribute(mma_gemm_h<11>,
                         cudaFuncAttributeMaxDynamicSharedMemorySize, SMEM_GEMM);

    // 0-1. positional encoding + embedding (+ bias concat folded in)
    pe_kernel<<<(S_ * D_ + 255) / 256, 256>>>(pe);
    embed_kernel<<<(BS_ * D_ / 4 + 255) / 256, 256>>>(tokens, emb, pe, x, xh,
                                                      bq, bk, bv, bqkv);

    // 2-3. weight prep (merged transposes)
    qkvT_kernel<<<dim3(2, 32, 48), dim3(32, 8)>>>(Wq, Wk, Wv, WqkvTh);
    transpose_all<<<9216, 256>>>(Wo, WoTh, W1, W1Th, W2, W2Th);

    // 4. fused QKV projection (bias + fp16 output)
    mma_gemm_h<9><<<dim3(N_QKV / 128, BS_ / 128), 128, SMEM_GEMM>>>(
        xh, WqkvTh, QKVh, bqkv, nullptr, BS_, N_QKV, D_);

    // 5. attention (fp16 MMA, register softmax)
    attention_kernel<<<B_ * H_, 256, ATT_SMEM>>>(QKVh, ctxh);

    // 6-7. output projection (unsplit, bias+residual fused, fp32 out) + LN1
    mma_gemm_h<5><<<dim3(D_ / 128, BS_ / 128), 128, SMEM_GEMM>>>(
        ctxh, WoTh, t1, bo, x, BS_, D_, D_);
    lnred_kernel<false, true><<<BS_, 256>>>(t1, nullptr, nullptr, nullptr,
                                            gamma1, beta1, x1, x1h);

    // 8-9. FFN: W1 (bias+relu+fp16 out), W2 (split-K 2)
    mma_gemm_h<11><<<dim3(F_ / 128, BS_ / 128), 128, SMEM_GEMM>>>(
        x1h, W1Th, ffhh, b1, nullptr, BS_, F_, D_);
    mma_gemm_h<0><<<dim3(D_ / 128, BS_ / 128, 2), 128, SMEM_GEMM>>>(
        ffhh, W2Th, t1, nullptr, nullptr, BS_, D_, F_);

    // 10. fused reduce + LN2 -> output
    lnred_kernel<true, false><<<BS_, 256>>>(t1, t1 + (size_t)BS_ * D_, b2, x1,
                                            gamma2, beta2, out, nullptr);
}